// round 3
// baseline (speedup 1.0000x reference)
#include <cuda_runtime.h>

static constexpr int B = 64;
static constexpr int N = 512 * 512;          // 262144 floats per row
static constexpr int N4 = N / 4;             // 65536 float4 per row
static constexpr int BLOCKS_PER_ROW = 32;
static constexpr int THREADS = 256;
static constexpr int VEC_PER_THREAD = N4 / (BLOCKS_PER_ROW * THREADS); // 8
static constexpr int NPART = B * BLOCKS_PER_ROW;                      // 2048

// Scratch: per-block partials, fully overwritten each launch (no init needed).
__device__ float g_part_ps[NPART];
__device__ float g_part_ts[NPART];
__device__ float g_part_in[NPART];

__global__ __launch_bounds__(THREADS) void dice_partial_kernel(
    const float* __restrict__ pred, const float* __restrict__ target)
{
    const int row = blockIdx.y;
    const long long row_base = (long long)row * N4;
    const int chunk = blockIdx.x * (THREADS * VEC_PER_THREAD) + threadIdx.x;

    const float4* __restrict__ p4 = reinterpret_cast<const float4*>(pred) + row_base;
    const float4* __restrict__ t4 = reinterpret_cast<const float4*>(target) + row_base;

    float ps = 0.f, ts = 0.f, in = 0.f;
#pragma unroll
    for (int v = 0; v < VEC_PER_THREAD; v++) {
        const int idx = chunk + v * THREADS;   // coalesced, stride THREADS
        float4 p = p4[idx];
        float4 t = t4[idx];
        ps += (p.x + p.y) + (p.z + p.w);
        ts += (t.x + t.y) + (t.z + t.w);
        in += p.x * t.x + p.y * t.y + p.z * t.z + p.w * t.w;
    }

    // warp reduce
#pragma unroll
    for (int off = 16; off > 0; off >>= 1) {
        ps += __shfl_down_sync(0xffffffffu, ps, off);
        ts += __shfl_down_sync(0xffffffffu, ts, off);
        in += __shfl_down_sync(0xffffffffu, in, off);
    }

    __shared__ float s_ps[THREADS / 32];
    __shared__ float s_ts[THREADS / 32];
    __shared__ float s_in[THREADS / 32];
    const int lane = threadIdx.x & 31;
    const int wid  = threadIdx.x >> 5;
    if (lane == 0) { s_ps[wid] = ps; s_ts[wid] = ts; s_in[wid] = in; }
    __syncthreads();

    if (wid == 0) {
        ps = (lane < THREADS / 32) ? s_ps[lane] : 0.f;
        ts = (lane < THREADS / 32) ? s_ts[lane] : 0.f;
        in = (lane < THREADS / 32) ? s_in[lane] : 0.f;
#pragma unroll
        for (int off = 4; off > 0; off >>= 1) {
            ps += __shfl_down_sync(0xffffffffu, ps, off);
            ts += __shfl_down_sync(0xffffffffu, ts, off);
            in += __shfl_down_sync(0xffffffffu, in, off);
        }
        if (lane == 0) {
            const int slot = row * BLOCKS_PER_ROW + blockIdx.x;
            g_part_ps[slot] = ps;
            g_part_ts[slot] = ts;
            g_part_in[slot] = in;
        }
    }
}

// One block, 1024 threads. Warp `wid` reduces the 32 partials of row `wid`
// (slots 32*wid..32*wid+31) and of row 32+wid (slots 1024+32*wid..+31).
__global__ __launch_bounds__(1024) void dice_final_kernel(float* __restrict__ out) {
    const float SMOOTH = 1.0f;
    const int tid  = threadIdx.x;          // 0..1023
    const int lane = tid & 31;
    const int wid  = tid >> 5;             // 0..31

    __shared__ float s_loss[B];            // one loss per row

#pragma unroll
    for (int half = 0; half < 2; half++) {
        const int slot = half * 1024 + tid;
        const int row  = half * 32 + wid;
        float ps = g_part_ps[slot];
        float ts = g_part_ts[slot];
        float in = g_part_in[slot];
#pragma unroll
        for (int off = 16; off > 0; off >>= 1) {
            ps += __shfl_down_sync(0xffffffffu, ps, off);
            ts += __shfl_down_sync(0xffffffffu, ts, off);
            in += __shfl_down_sync(0xffffffffu, in, off);
        }
        if (lane == 0) {
            float dice_loss = 1.0f - (2.0f * in + SMOOTH) / (ps + ts + SMOOTH);
            float zero_loss = ps / (float)N;
            s_loss[row] = (ts == 0.0f) ? zero_loss : dice_loss;
        }
    }
    __syncthreads();

    // Reduce 64 losses -> mean.
    if (wid < 2) {
        float v = s_loss[wid * 32 + lane];
#pragma unroll
        for (int off = 16; off > 0; off >>= 1)
            v += __shfl_down_sync(0xffffffffu, v, off);
        if (lane == 0) s_loss[wid] = v;   // reuse slots 0,1
    }
    __syncthreads();
    if (tid == 0) out[0] = (s_loss[0] + s_loss[1]) / (float)B;
}

extern "C" void kernel_launch(void* const* d_in, const int* in_sizes, int n_in,
                              void* d_out, int out_size) {
    const float* pred   = (const float*)d_in[0];
    const float* target = (const float*)d_in[1];
    float* out = (float*)d_out;

    dim3 grid(BLOCKS_PER_ROW, B);
    dice_partial_kernel<<<grid, THREADS>>>(pred, target);
    dice_final_kernel<<<1, 1024>>>(out);
}